// round 12
// baseline (speedup 1.0000x reference)
#include <cuda_runtime.h>
#include <cuda_bf16.h>
#include <cstdint>

// CostVolumeCorrelationLayer via banded bf16-split GEMM on mma.sync (m16n8k16).
// Round-12: 2 output rows per CTA (shared F2 halo rows: 10 B-fills per 2 rows
// instead of 18) + double-buffered cp.async pipeline (fill r+2 overlaps mma r+1).
// Kernel 1 pre-splits F2 fp32 -> bf16 hi/lo scratch once (unchanged from R11).

#define BB 8
#define HH 128
#define WW 128
#define CC 128
#define KD 81
#define NTH1 256              // split kernel
#define NTH2 512              // main kernel: 16 warps = (row 0..1) x (m-tile 0..7)

#define ROWB 272              // bytes per 128-ch bf16 row (+16B pad); 272%128=16 -> ldmatrix conflict-free
#define B_LO_REL 36992        // 136*272, lo half within a buffer
#define BUF_SZ  73984         // hi+lo per buffer
#define SMEM_BYTES (2 * BUF_SZ)   // 147968
#define A_LO_REL 34816        // 128*272, within staging region

#define NELEM ((size_t)BB * HH * WW * CC)
__device__ __align__(16) __nv_bfloat16 g_hi[NELEM];   // 32 MB scratch
__device__ __align__(16) __nv_bfloat16 g_lo[NELEM];   // 32 MB scratch

__device__ __forceinline__ uint32_t smem_u32(const void* p) {
    uint32_t a;
    asm("{ .reg .u64 t; cvta.to.shared.u64 t, %1; cvt.u32.u64 %0, t; }" : "=r"(a) : "l"(p));
    return a;
}
__device__ __forceinline__ void ldsm_x4(uint32_t* r, uint32_t addr) {
    asm volatile("ldmatrix.sync.aligned.m8n8.x4.shared.b16 {%0,%1,%2,%3}, [%4];"
                 : "=r"(r[0]), "=r"(r[1]), "=r"(r[2]), "=r"(r[3]) : "r"(addr));
}
__device__ __forceinline__ void ldsm_x2(uint32_t* r, uint32_t addr) {
    asm volatile("ldmatrix.sync.aligned.m8n8.x2.shared.b16 {%0,%1}, [%2];"
                 : "=r"(r[0]), "=r"(r[1]) : "r"(addr));
}
__device__ __forceinline__ void mma16816(float* d, const uint32_t* a, const uint32_t* b) {
    asm volatile("mma.sync.aligned.m16n8k16.row.col.f32.bf16.bf16.f32 "
                 "{%0,%1,%2,%3}, {%4,%5,%6,%7}, {%8,%9}, {%0,%1,%2,%3};"
                 : "+f"(d[0]), "+f"(d[1]), "+f"(d[2]), "+f"(d[3])
                 : "r"(a[0]), "r"(a[1]), "r"(a[2]), "r"(a[3]), "r"(b[0]), "r"(b[1]));
}
__device__ __forceinline__ void cp16(uint32_t dst, const void* src) {
    asm volatile("cp.async.cg.shared.global [%0], [%1], 16;" :: "r"(dst), "l"(src));
}

// hi = truncate-to-bf16 (exact residual), lo = rn(v - hi). 4 channels.
__device__ __forceinline__ void split4(float4 v, uint2& hi, uint2& lo) {
    uint32_t u0 = __float_as_uint(v.x), u1 = __float_as_uint(v.y);
    uint32_t u2 = __float_as_uint(v.z), u3 = __float_as_uint(v.w);
    hi.x = __byte_perm(u0, u1, 0x7632);
    hi.y = __byte_perm(u2, u3, 0x7632);
    float l0 = v.x - __uint_as_float(u0 & 0xFFFF0000u);
    float l1 = v.y - __uint_as_float(u1 & 0xFFFF0000u);
    float l2 = v.z - __uint_as_float(u2 & 0xFFFF0000u);
    float l3 = v.w - __uint_as_float(u3 & 0xFFFF0000u);
    asm("cvt.rn.bf16x2.f32 %0, %1, %2;" : "=r"(lo.x) : "f"(l1), "f"(l0));
    asm("cvt.rn.bf16x2.f32 %0, %1, %2;" : "=r"(lo.y) : "f"(l3), "f"(l2));
}

// ---------------- Kernel 1: F2 fp32 -> bf16 hi/lo scratch ----------------
__global__ __launch_bounds__(NTH1)
void split_kernel(const float* __restrict__ F2)
{
    const int row = blockIdx.x;
    const float* src = F2 + (size_t)row * WW * CC;
    __nv_bfloat16* hp = g_hi + (size_t)row * WW * CC;
    __nv_bfloat16* lp = g_lo + (size_t)row * WW * CC;
#pragma unroll 4
    for (int it = threadIdx.x; it < 128 * 32; it += NTH1) {
        int x = it >> 5, q = it & 31;
        float4 v = __ldcg(reinterpret_cast<const float4*>(src + (size_t)x * CC + 4 * q));
        uint2 hi, lo;
        split4(v, hi, lo);
        *reinterpret_cast<uint2*>(hp + (size_t)x * CC + 4 * q) = hi;
        *reinterpret_cast<uint2*>(lp + (size_t)x * CC + 4 * q) = lo;
    }
}

// ---------------- Kernel 2: banded GEMM, 2 rows/CTA, pipelined B ----------------
__global__ __launch_bounds__(NTH2, 1)
void corr_mma_kernel(const float* __restrict__ F1,
                     float* __restrict__ out)
{
    extern __shared__ char smem[];
    const uint32_t sb  = smem_u32(smem);
    const int tid  = threadIdx.x;
    const int w    = tid >> 5;
    const int lane = tid & 31;
    const int row  = w >> 3;            // output row within CTA
    const int m    = w & 7;             // m-tile
    const int y0 = blockIdx.x * 2, b = blockIdx.y;

    // ---- stage both A rows (bf16 hi/lo) into the two buffer regions ----
#pragma unroll 4
    for (int it = tid; it < 2 * 128 * 32; it += NTH2) {
        int rr = it >> 12, rem = it & 4095;
        int x = rem >> 5, q = rem & 31;
        const float* f1p = F1 + ((size_t)(b * HH + y0 + rr)) * WW * CC;
        float4 v = __ldcg(reinterpret_cast<const float4*>(f1p + (size_t)x * CC + 4 * q));
        uint2 hi, lo;
        split4(v, hi, lo);
        char* base = smem + rr * BUF_SZ + x * ROWB + 8 * q;
        *reinterpret_cast<uint2*>(base)            = hi;
        *reinterpret_cast<uint2*>(base + A_LO_REL) = lo;
    }
    __syncthreads();

    // ---- A fragments (8 k-steps, hi+lo) -> registers (own row's region) ----
    uint32_t ahi[8][4], alo[8][4];
    {
        uint32_t arow = sb + (uint32_t)row * BUF_SZ
                      + (uint32_t)(16 * m + (lane & 15)) * ROWB + ((lane >> 4) << 4);
#pragma unroll
        for (int s = 0; s < 8; s++) ldsm_x4(ahi[s], arow + 32 * s);
        arow += A_LO_REL;
#pragma unroll
        for (int s = 0; s < 8; s++) ldsm_x4(alo[s], arow + 32 * s);
    }
    __syncthreads();   // A reads done -> regions become B buffers

    // ---- zero border j-columns {0..3,132..135} in both buffers (hi+lo) ----
    for (int k = tid; k < 2 * 2 * 8 * 17; k += NTH2) {
        int c  = k % 17;
        int t  = k / 17;          // 0..31: buf(1b) | half(1b) | jb(3b)
        int jb = t & 7, half = (t >> 3) & 1, bf = t >> 4;
        int j  = (jb < 4) ? jb : (jb + 128);
        *reinterpret_cast<uint4*>(smem + bf * BUF_SZ + half * B_LO_REL + j * ROWB + 16 * c)
            = make_uint4(0, 0, 0, 0);
    }
    __syncthreads();

    // ---- B fragment base offsets (buffer-relative) ----
    uint32_t brel[3];
#pragma unroll
    for (int nt = 0; nt < 3; nt++)
        brel[nt] = (uint32_t)(16 * m + 8 * nt + (lane & 7)) * ROWB + ((lane & 8) ? 16 : 0);

    const float inv = 1.0f / 128.0f;
    const int x0 = 16 * m;

    // fill helper expressed inline: B row r -> buffer r&1 (j = 4..131 interior)
#define FILL_B(r)                                                                   \
    {                                                                               \
        const int yy = y0 + (r) - 4;                                                \
        const uint32_t bb = sb + (uint32_t)((r) & 1) * BUF_SZ;                      \
        if (yy >= 0 && yy < HH) {                                                   \
            const size_t ro = (size_t)(b * HH + yy) * WW * CC;                      \
            _Pragma("unroll")                                                       \
            for (int k = tid; k < 4096; k += NTH2) {                                \
                int hl = k >> 11, rm = k & 2047;                                    \
                int x = rm >> 4, q = rm & 15;                                       \
                uint32_t d = bb + (uint32_t)hl * B_LO_REL + (uint32_t)(x + 4) * ROWB + 16 * q; \
                const __nv_bfloat16* s = (hl ? g_lo : g_hi) + ro + (size_t)x * CC + 8 * q;     \
                cp16(d, s);                                                         \
            }                                                                       \
        } else {                                                                    \
            _Pragma("unroll")                                                       \
            for (int k = tid; k < 4096; k += NTH2) {                                \
                int hl = k >> 11, rm = k & 2047;                                    \
                int x = rm >> 4, q = rm & 15;                                       \
                uint32_t d = bb + (uint32_t)hl * B_LO_REL + (uint32_t)(x + 4) * ROWB + 16 * q; \
                *reinterpret_cast<uint4*>(smem + (d - sb)) = make_uint4(0, 0, 0, 0);\
            }                                                                       \
        }                                                                           \
        asm volatile("cp.async.commit_group;" ::: "memory");                        \
    }

    FILL_B(0)
    FILL_B(1)

    for (int r = 0; r < 10; r++) {
        if (r < 9) { asm volatile("cp.async.wait_group 1;" ::: "memory"); }
        else       { asm volatile("cp.async.wait_group 0;" ::: "memory"); }
        __syncthreads();                       // B(r) visible to all

        const int dy = r - row;
        if (dy >= 0 && dy <= 8) {
            const uint32_t bb = sb + (uint32_t)(r & 1) * BUF_SZ;
            float acc[3][4];
#pragma unroll
            for (int nt = 0; nt < 3; nt++)
#pragma unroll
                for (int e = 0; e < 4; e++) acc[nt][e] = 0.f;

#pragma unroll
            for (int s = 0; s < 8; s++) {
#pragma unroll
                for (int nt = 0; nt < 3; nt++) {
                    uint32_t bh[2], bl[2];
                    ldsm_x2(bh, bb + brel[nt] + 32 * s);
                    mma16816(acc[nt], ahi[s], bh);                 // hi*hi
                    mma16816(acc[nt], alo[s], bh);                 // lo*hi
                    ldsm_x2(bl, bb + B_LO_REL + brel[nt] + 32 * s);
                    mma16816(acc[nt], ahi[s], bl);                 // hi*lo
                }
            }

            // banded epilogue: dx = j - x in [0,8]
            const int rbr = lane >> 2, cb = 2 * (lane & 3);
#pragma unroll
            for (int nt = 0; nt < 3; nt++) {
                const int n0 = 16 * m + 8 * nt;
#pragma unroll
                for (int h = 0; h < 2; h++) {
                    const int x = x0 + rbr + 8 * h;
                    float* op = out + (((size_t)(b * HH + y0 + row)) * WW + x) * KD + 9 * dy;
#pragma unroll
                    for (int e = 0; e < 2; e++) {
                        const int dx = n0 + cb + e - x;
                        if (dx >= 0 && dx <= 8) {
                            float v = acc[nt][2 * h + e] * inv;
                            v = v > 0.f ? v : 0.1f * v;
                            op[dx] = v;
                        }
                    }
                }
            }
        }
        __syncthreads();                       // B(r) reads done -> buffer reusable
        if (r + 2 <= 9) FILL_B(r + 2)          // lands during mma(r+1)
    }
#undef FILL_B
}

extern "C" void kernel_launch(void* const* d_in, const int* in_sizes, int n_in,
                              void* d_out, int out_size)
{
    const float* F1 = (const float*)d_in[0];
    const float* F2 = (const float*)d_in[1];
    float* out = (float*)d_out;

    cudaFuncSetAttribute(corr_mma_kernel, cudaFuncAttributeMaxDynamicSharedMemorySize, SMEM_BYTES);

    split_kernel<<<BB * HH, NTH1>>>(F2);       // F2 -> bf16 hi/lo scratch (once)

    dim3 grid(HH / 2, BB);                     // (y-pair, b)
    corr_mma_kernel<<<grid, NTH2, SMEM_BYTES>>>(F1, out);
}

// round 13
// speedup vs baseline: 1.1448x; 1.1448x over previous
#include <cuda_runtime.h>
#include <cuda_bf16.h>
#include <cstdint>

// CostVolumeCorrelationLayer via banded bf16-split GEMM on mma.sync (m16n8k16).
// Round-13: R11 shape (256 thr, 1 row/CTA, 2 CTAs/SM) with a REAL cp.async
// pipeline: B-hi double-buffered (fill dy+1 overlaps mma dy), B-lo single
// (only 32KB exposed per dy, covered by the co-resident CTA). ldsm_x4 B loads.
// Kernel 1 pre-splits F2 fp32 -> bf16 hi/lo scratch once.

#define BB 8
#define HH 128
#define WW 128
#define CC 128
#define KD 81
#define NTH 256

#define ROWB 272                 // bytes per 136-col bf16 row slot; 272%128=16 -> ldmatrix conflict-free
#define HBUF 36992               // 136*272 one hi buffer
#define H0_OFF 0
#define H1_OFF 36992
#define L_OFF  73984
#define SMEM_BYTES 110976        // 3*36992 -> 2 CTAs/SM (221952 <= 228KB)
#define A_HI_OFF 0               // A staged in H0/H1 regions before the loop
#define A_LO_OFF 36992

#define NELEM ((size_t)BB * HH * WW * CC)
__device__ __align__(16) __nv_bfloat16 g_hi[NELEM];   // 32 MB scratch
__device__ __align__(16) __nv_bfloat16 g_lo[NELEM];   // 32 MB scratch

__device__ __forceinline__ uint32_t smem_u32(const void* p) {
    uint32_t a;
    asm("{ .reg .u64 t; cvta.to.shared.u64 t, %1; cvt.u32.u64 %0, t; }" : "=r"(a) : "l"(p));
    return a;
}
__device__ __forceinline__ void ldsm_x4(uint32_t* r, uint32_t addr) {
    asm volatile("ldmatrix.sync.aligned.m8n8.x4.shared.b16 {%0,%1,%2,%3}, [%4];"
                 : "=r"(r[0]), "=r"(r[1]), "=r"(r[2]), "=r"(r[3]) : "r"(addr));
}
__device__ __forceinline__ void mma16816(float* d, const uint32_t* a, const uint32_t* b) {
    asm volatile("mma.sync.aligned.m16n8k16.row.col.f32.bf16.bf16.f32 "
                 "{%0,%1,%2,%3}, {%4,%5,%6,%7}, {%8,%9}, {%0,%1,%2,%3};"
                 : "+f"(d[0]), "+f"(d[1]), "+f"(d[2]), "+f"(d[3])
                 : "r"(a[0]), "r"(a[1]), "r"(a[2]), "r"(a[3]), "r"(b[0]), "r"(b[1]));
}
__device__ __forceinline__ void cp16(uint32_t dst, const void* src) {
    asm volatile("cp.async.cg.shared.global [%0], [%1], 16;" :: "r"(dst), "l"(src));
}

// hi = truncate-to-bf16 (exact residual), lo = rn(v - hi). 4 channels.
__device__ __forceinline__ void split4(float4 v, uint2& hi, uint2& lo) {
    uint32_t u0 = __float_as_uint(v.x), u1 = __float_as_uint(v.y);
    uint32_t u2 = __float_as_uint(v.z), u3 = __float_as_uint(v.w);
    hi.x = __byte_perm(u0, u1, 0x7632);
    hi.y = __byte_perm(u2, u3, 0x7632);
    float l0 = v.x - __uint_as_float(u0 & 0xFFFF0000u);
    float l1 = v.y - __uint_as_float(u1 & 0xFFFF0000u);
    float l2 = v.z - __uint_as_float(u2 & 0xFFFF0000u);
    float l3 = v.w - __uint_as_float(u3 & 0xFFFF0000u);
    asm("cvt.rn.bf16x2.f32 %0, %1, %2;" : "=r"(lo.x) : "f"(l1), "f"(l0));
    asm("cvt.rn.bf16x2.f32 %0, %1, %2;" : "=r"(lo.y) : "f"(l3), "f"(l2));
}

// ---------------- Kernel 1: F2 fp32 -> bf16 hi/lo scratch ----------------
__global__ __launch_bounds__(NTH)
void split_kernel(const float* __restrict__ F2)
{
    const int row = blockIdx.x;
    const float* src = F2 + (size_t)row * WW * CC;
    __nv_bfloat16* hp = g_hi + (size_t)row * WW * CC;
    __nv_bfloat16* lp = g_lo + (size_t)row * WW * CC;
#pragma unroll
    for (int it = threadIdx.x; it < 128 * 16; it += NTH) {
        int x = it >> 4, q = it & 15;
        const float* s = src + (size_t)x * CC + 8 * q;
        float4 v0 = __ldcg(reinterpret_cast<const float4*>(s));
        float4 v1 = __ldcg(reinterpret_cast<const float4*>(s + 4));
        uint2 h0, l0, h1, l1;
        split4(v0, h0, l0); split4(v1, h1, l1);
        *reinterpret_cast<uint4*>(hp + (size_t)x * CC + 8 * q) = make_uint4(h0.x, h0.y, h1.x, h1.y);
        *reinterpret_cast<uint4*>(lp + (size_t)x * CC + 8 * q) = make_uint4(l0.x, l0.y, l1.x, l1.y);
    }
}

// ---------------- Kernel 2: banded GEMM, pipelined B fills ----------------
__global__ __launch_bounds__(NTH, 2)
void corr_mma_kernel(const float* __restrict__ F1,
                     float* __restrict__ out)
{
    extern __shared__ char smem[];
    const uint32_t sb  = smem_u32(smem);
    const int tid  = threadIdx.x;
    const int m    = tid >> 5;          // m-tile 0..7
    const int lane = tid & 31;
    const int y = blockIdx.x, b = blockIdx.y;

    // ---- stage A = F1 row (bf16 hi/lo) into H0/H1 regions ----
    const float* f1p = F1 + ((size_t)(b * HH + y)) * WW * CC;
#pragma unroll 4
    for (int it = tid; it < 128 * 32; it += NTH) {
        int x = it >> 5, q = it & 31;
        float4 v = __ldcg(reinterpret_cast<const float4*>(f1p + (size_t)x * CC + 4 * q));
        uint2 hi, lo;
        split4(v, hi, lo);
        *reinterpret_cast<uint2*>(smem + A_HI_OFF + x * ROWB + 8 * q) = hi;
        *reinterpret_cast<uint2*>(smem + A_LO_OFF + x * ROWB + 8 * q) = lo;
    }
    __syncthreads();

    // ---- A fragments (8 k-steps, hi+lo) -> registers ----
    uint32_t ahi[8][4], alo[8][4];
    {
        uint32_t arow = sb + A_HI_OFF + (uint32_t)(16 * m + (lane & 15)) * ROWB + ((lane >> 4) << 4);
#pragma unroll
        for (int s = 0; s < 8; s++) ldsm_x4(ahi[s], arow + 32 * s);
        arow += (uint32_t)(A_LO_OFF - A_HI_OFF);
#pragma unroll
        for (int s = 0; s < 8; s++) ldsm_x4(alo[s], arow + 32 * s);
    }
    __syncthreads();   // A smem reads done -> regions become B buffers

    // ---- zero border j-columns {0..3,132..135} in H0, H1, L (once) ----
    for (int k = tid; k < 3 * 8 * 17; k += NTH) {
        int c  = k % 17;
        int t  = k / 17;           // region(2b) | jb(3b)
        int jb = t & 7, reg = t >> 3;
        int j  = (jb < 4) ? jb : (jb + 128);
        *reinterpret_cast<uint4*>(smem + reg * HBUF + j * ROWB + 16 * c) = make_uint4(0, 0, 0, 0);
    }

    // B fragment base offsets for ldsm_x4 (2 k-steps): lane-group byte 0/16/32/48
    uint32_t brel4[3];
#pragma unroll
    for (int nt = 0; nt < 3; nt++)
        brel4[nt] = (uint32_t)(16 * m + 8 * nt + (lane & 7)) * ROWB + 16 * (uint32_t)(lane >> 3);

    const float inv = 1.0f / 128.0f;
    const int x0 = 16 * m;

    // fill helpers: interior j=4..131; 8 cp16/thread; always commit (group counting)
#define FILL(r, HALF, OFFEXPR)                                                        \
    {                                                                                 \
        const int yy = y + (r) - 4;                                                   \
        const uint32_t bbase = sb + (OFFEXPR);                                        \
        if (yy >= 0 && yy < HH) {                                                     \
            const size_t ro = (size_t)(b * HH + yy) * WW * CC;                        \
            _Pragma("unroll")                                                         \
            for (int k = tid; k < 2048; k += NTH) {                                   \
                int x = k >> 4, q = k & 15;                                           \
                cp16(bbase + (uint32_t)(x + 4) * ROWB + 16 * q,                       \
                     HALF + ro + (size_t)x * CC + 8 * q);                             \
            }                                                                         \
        } else {                                                                      \
            _Pragma("unroll")                                                         \
            for (int k = tid; k < 2048; k += NTH) {                                   \
                int x = k >> 4, q = k & 15;                                           \
                *reinterpret_cast<uint4*>(smem + (OFFEXPR) + (x + 4) * ROWB + 16 * q) \
                    = make_uint4(0, 0, 0, 0);                                         \
            }                                                                         \
        }                                                                             \
        asm volatile("cp.async.commit_group;" ::: "memory");                          \
    }

    // prologue: groups in order = lo(0), hi(0)->H0, hi(1)->H1
    FILL(0, g_lo, L_OFF)
    FILL(0, g_hi, H0_OFF)
    FILL(1, g_hi, H1_OFF)

    for (int dy = 0; dy < 9; dy++) {
        if (dy < 8) { asm volatile("cp.async.wait_group 1;" ::: "memory"); }
        else        { asm volatile("cp.async.wait_group 0;" ::: "memory"); }
        __syncthreads();                       // hi(dy) + lo(dy) visible

        const uint32_t bh_base = sb + (uint32_t)(dy & 1) * HBUF;
        const uint32_t bl_base = sb + L_OFF;

        float acc[3][4];
#pragma unroll
        for (int nt = 0; nt < 3; nt++)
#pragma unroll
            for (int e = 0; e < 4; e++) acc[nt][e] = 0.f;

#pragma unroll
        for (int s = 0; s < 8; s += 2) {
#pragma unroll
            for (int nt = 0; nt < 3; nt++) {
                uint32_t bh[4], bl[4];
                ldsm_x4(bh, bh_base + brel4[nt] + 32 * s);   // k-steps s, s+1
                mma16816(acc[nt], ahi[s],     bh);           // hi*hi (s)
                mma16816(acc[nt], alo[s],     bh);           // lo*hi (s)
                mma16816(acc[nt], ahi[s + 1], bh + 2);       // hi*hi (s+1)
                mma16816(acc[nt], alo[s + 1], bh + 2);       // lo*hi (s+1)
                ldsm_x4(bl, bl_base + brel4[nt] + 32 * s);
                mma16816(acc[nt], ahi[s],     bl);           // hi*lo (s)
                mma16816(acc[nt], ahi[s + 1], bl + 2);       // hi*lo (s+1)
            }
        }

        // banded epilogue: dx = j - x in [0,8]
        const int rbr = lane >> 2, cb = 2 * (lane & 3);
#pragma unroll
        for (int nt = 0; nt < 3; nt++) {
            const int n0 = 16 * m + 8 * nt;
#pragma unroll
            for (int h = 0; h < 2; h++) {
                const int x = x0 + rbr + 8 * h;
                float* op = out + (((size_t)(b * HH + y)) * WW + x) * KD + 9 * dy;
#pragma unroll
                for (int e = 0; e < 2; e++) {
                    const int dx = n0 + cb + e - x;
                    if (dx >= 0 && dx <= 8) {
                        float v = acc[nt][2 * h + e] * inv;
                        v = v > 0.f ? v : 0.1f * v;
                        op[dx] = v;
                    }
                }
            }
        }
        __syncthreads();                       // B(dy) reads done -> buffers reusable

        if (dy + 1 <= 8) FILL(dy + 1, g_lo, L_OFF)                        // exposed next iter (32KB)
        if (dy + 2 <= 8) FILL(dy + 2, g_hi, ((uint32_t)(dy & 1) * HBUF))  // hidden behind mma(dy+1)
    }
#undef FILL
}

extern "C" void kernel_launch(void* const* d_in, const int* in_sizes, int n_in,
                              void* d_out, int out_size)
{
    const float* F1 = (const float*)d_in[0];
    const float* F2 = (const float*)d_in[1];
    float* out = (float*)d_out;

    cudaFuncSetAttribute(corr_mma_kernel, cudaFuncAttributeMaxDynamicSharedMemorySize, SMEM_BYTES);

    split_kernel<<<BB * HH, NTH>>>(F2);        // F2 -> bf16 hi/lo scratch (once)

    dim3 grid(HH, BB);                         // (y, b): y-adjacent CTAs reuse scratch in L2
    corr_mma_kernel<<<grid, NTH, SMEM_BYTES>>>(F1, out);
}